// round 3
// baseline (speedup 1.0000x reference)
#include <cuda_runtime.h>
#include <cuda_fp16.h>

#define B_ 512
#define T_ 365
#define D_ 16
#define S_ 32
#define H_ 256

// ---------------- device scratch ----------------
// Packed weights, global-j layout: [k2*256 + j] -> uint4 of 4 gates (i,f,g,o),
// each uint = half2(W[g*256+j][2k2], W[g*256+j][2k2+1])
__device__ uint4  g_Whh0p[128 * 256];
__device__ uint4  g_Wih1p[128 * 256];
__device__ uint4  g_Whh1p[128 * 256];
__device__ float4 g_Wih0t[16 * 256];   // [k*256 + j] -> float4 over gates
__device__ float4 g_b0v[256];
__device__ float4 g_b1v[256];
__device__ float  g_h0[B_ * H_];

// ---------------- preprocessing kernels ----------------
__global__ void k_pack(const float* __restrict__ W, int which) {
    uint4* dst = (which == 0) ? g_Whh0p : (which == 1) ? g_Wih1p : g_Whh1p;
    int e = blockIdx.x * blockDim.x + threadIdx.x;
    if (e >= 128 * 256) return;
    int k2 = e >> 8, j = e & 255;
    uint4 v;
#pragma unroll
    for (int g = 0; g < 4; g++) {
        float a = W[(g * H_ + j) * 256 + 2 * k2];
        float b = W[(g * H_ + j) * 256 + 2 * k2 + 1];
        __half2 h = __floats2half2_rn(a, b);
        ((unsigned*)&v)[g] = *reinterpret_cast<unsigned*>(&h);
    }
    dst[e] = v;
}

__global__ void k_wih0t(const float* __restrict__ W) {
    int e = blockIdx.x * blockDim.x + threadIdx.x;
    if (e >= 16 * 256) return;
    int k = e >> 8, j = e & 255;
    float4 v;
#pragma unroll
    for (int g = 0; g < 4; g++)
        ((float*)&v)[g] = W[(g * H_ + j) * D_ + k];
    g_Wih0t[e] = v;
}

__global__ void k_bias(const float* __restrict__ bih0, const float* __restrict__ bhh0,
                       const float* __restrict__ bih1, const float* __restrict__ bhh1) {
    int j = blockIdx.x * blockDim.x + threadIdx.x;
    if (j >= H_) return;
    float4 v0, v1;
#pragma unroll
    for (int g = 0; g < 4; g++) {
        ((float*)&v0)[g] = bih0[g * H_ + j] + bhh0[g * H_ + j];
        ((float*)&v1)[g] = bih1[g * H_ + j] + bhh1[g * H_ + j];
    }
    g_b0v[j] = v0;
    g_b1v[j] = v1;
}

__global__ void k_h0(const float* __restrict__ xst, const float* __restrict__ Ws,
                     const float* __restrict__ bs) {
    int e = blockIdx.x * blockDim.x + threadIdx.x;
    if (e >= B_ * H_) return;
    int b = e >> 8, j = e & 255;
    float s = bs[j];
#pragma unroll
    for (int k = 0; k < S_; k++)
        s += xst[b * S_ + k] * Ws[j * S_ + k];
    g_h0[e] = s;
}

// ---------------- main cluster kernel ----------------
union U64F2 { unsigned long long u; float2 f; };
__device__ __forceinline__ void fma2(unsigned long long& d, unsigned long long a,
                                     unsigned long long b) {
    asm("fma.rn.f32x2 %0, %1, %2, %0;" : "+l"(d) : "l"(a), "l"(b));
}
__device__ __forceinline__ unsigned long long f2u(float2 v) { U64F2 t; t.f = v; return t.u; }
__device__ __forceinline__ float2 u2f(unsigned long long v) { U64F2 t; t.u = v; return t.f; }
__device__ __forceinline__ float sigm(float v) { return 1.0f / (1.0f + __expf(-v)); }
__device__ __forceinline__ unsigned smem_u32(const void* p) {
    unsigned a;
    asm("{ .reg .u64 t; cvta.to.shared.u64 t, %1; cvt.u32.u64 %0, t; }" : "=r"(a) : "l"(p));
    return a;
}
#define CLUSTER_ARRIVE() asm volatile("barrier.cluster.arrive.aligned;" ::: "memory")
#define CLUSTER_WAIT()   asm volatile("barrier.cluster.wait.aligned;" ::: "memory")

// SMEM layout (dynamic, 231424 bytes total):
//   [0, 196608)        uint4 ws[3][128][32]   weight slices (fp16-packed)
//   [196608, 212992)   half  h0b[32][256]     full h0 for this cluster's rows
//   [212992, 229376)   half  h1b[32][256]
//   [229376, 231424)   scratch: float xs[32][16]  /  half stg[32][32]
#define W_OFF   0
#define H0_OFF  196608
#define H1_OFF  212992
#define SC_OFF  229376
#define SMEM_BYTES 231424

__global__ void __launch_bounds__(256, 1) __cluster_dims__(8, 1, 1)
lstm_main(const float* __restrict__ x, const float* __restrict__ Wo,
          const float* __restrict__ bo, float* __restrict__ out)
{
    extern __shared__ char smem[];
    uint4*  ws  = (uint4*)(smem + W_OFF);
    __half* h0b = (__half*)(smem + H0_OFF);
    __half* h1b = (__half*)(smem + H1_OFF);
    float*  xs  = (float*)(smem + SC_OFF);
    __half* stg = (__half*)(smem + SC_OFF);

    const int tid = threadIdx.x;
    const int jl = tid & 31;        // j within this CTA's slice
    const int rg = tid >> 5;        // row group (warp): rows 4*rg..4*rg+3
    unsigned rank;
    asm("mov.u32 %0, %%cluster_ctarank;" : "=r"(rank));
    const int baseRow = (blockIdx.x >> 3) * 32;
    const int jg = (int)rank * 32 + jl;     // global j this thread computes

    // ---- copy weight slices into SMEM (resident for whole kernel) ----
    for (int i = tid; i < 4096; i += 256) {
        int k2 = i >> 5, jj = i & 31;
        int src = k2 * 256 + (int)rank * 32 + jj;
        ws[i]        = g_Whh0p[src];
        ws[4096 + i] = g_Wih1p[src];
        ws[8192 + i] = g_Whh1p[src];
    }

    const float4 b0v = g_b0v[jg];
    const float4 b1v = g_b1v[jg];
    float wo[8];
#pragma unroll
    for (int m = 0; m < 8; m++) wo[m] = Wo[jl + 32 * m];
    const float bo0 = __ldg(bo);

    // ---- init h buffers (fp16) and c (fp32 regs) ----
    for (int i = tid; i < 32 * 256; i += 256) {
        __half hv = __float2half(g_h0[(baseRow + (i >> 8)) * 256 + (i & 255)]);
        h0b[i] = hv;
        h1b[i] = hv;
    }
    float c0[4], c1[4];
#pragma unroll
    for (int r = 0; r < 4; r++) {
        float v = g_h0[(baseRow + 4 * rg + r) * 256 + jg];
        c0[r] = v;
        c1[r] = v;
    }
    __syncthreads();
    CLUSTER_ARRIVE();
    CLUSTER_WAIT();

    const unsigned h0u = smem_u32(h0b);
    const unsigned h1u = smem_u32(h1b);
    const int prow = tid >> 3, pq = tid & 7;   // push mapping: 8B chunk per thread
    const unsigned pOff0 = h0u + (unsigned)(prow * 512 + ((int)rank * 32 + pq * 4) * 2);
    const unsigned pOff1 = h1u + (unsigned)(prow * 512 + ((int)rank * 32 + pq * 4) * 2);

    for (int t = 0; t < T_; t++) {
        // ---- stage x_t (warp-local rows) ----
        {
            int e = jl;
            xs[(4 * rg + (e >> 4)) * 16 + (e & 15)] =
                x[((baseRow + 4 * rg + (e >> 4)) * T_ + t) * D_ + (e & 15)];
            e = jl + 32;
            xs[(4 * rg + (e >> 4)) * 16 + (e & 15)] =
                x[((baseRow + 4 * rg + (e >> 4)) * T_ + t) * D_ + (e & 15)];
            __syncwarp();
        }

        // ---- phase A: layer-0 gates = b0 + x@Wih0^T + Whh0@h0 ----
        float aS[4][4];
#pragma unroll
        for (int r = 0; r < 4; r++) {
            aS[0][r] = b0v.x; aS[1][r] = b0v.y; aS[2][r] = b0v.z; aS[3][r] = b0v.w;
        }
#pragma unroll
        for (int k = 0; k < D_; k++) {
            float4 w = g_Wih0t[k * 256 + jg];
#pragma unroll
            for (int r = 0; r < 4; r++) {
                float xv = xs[(4 * rg + r) * 16 + k];
                aS[0][r] += w.x * xv; aS[1][r] += w.y * xv;
                aS[2][r] += w.z * xv; aS[3][r] += w.w * xv;
            }
        }

        unsigned long long acc[4][4];
#pragma unroll
        for (int g = 0; g < 4; g++)
#pragma unroll
            for (int r = 0; r < 4; r++) acc[g][r] = 0ull;

#pragma unroll 4
        for (int k2 = 0; k2 < 128; k2++) {
            uint4 wp = ws[k2 * 32 + jl];
            unsigned long long wg[4];
#pragma unroll
            for (int g = 0; g < 4; g++) {
                unsigned wv = ((const unsigned*)&wp)[g];
                wg[g] = f2u(__half22float2(*reinterpret_cast<__half2*>(&wv)));
            }
#pragma unroll
            for (int r = 0; r < 4; r++) {
                __half2 hh = *(const __half2*)(h0b + (4 * rg + r) * 256 + 2 * k2);
                unsigned long long hv = f2u(__half22float2(hh));
                fma2(acc[0][r], wg[0], hv);
                fma2(acc[1][r], wg[1], hv);
                fma2(acc[2][r], wg[2], hv);
                fma2(acc[3][r], wg[3], hv);
            }
        }
        CLUSTER_ARRIVE();   // #1: this CTA done reading old h0b

        float hn[4];
#pragma unroll
        for (int r = 0; r < 4; r++) {
            float2 vi = u2f(acc[0][r]), vf = u2f(acc[1][r]);
            float2 vg = u2f(acc[2][r]), vo = u2f(acc[3][r]);
            float gi = aS[0][r] + vi.x + vi.y;
            float gf = aS[1][r] + vf.x + vf.y;
            float gg = aS[2][r] + vg.x + vg.y;
            float go = aS[3][r] + vo.x + vo.y;
            float iv = sigm(gi), fv = sigm(gf), gv = tanhf(gg), ov = sigm(go);
            c0[r] = fv * c0[r] + iv * gv;
            hn[r] = ov * tanhf(c0[r]);
        }
#pragma unroll
        for (int r = 0; r < 4; r++)
            stg[(4 * rg + r) * 32 + jl] = __float2half(hn[r]);
        __syncthreads();    // stage complete (CTA-local)
        CLUSTER_WAIT();     // all CTAs done reading old h0b

        // ---- push new h0 slice to every CTA in cluster ----
        {
            unsigned long long v = *(const unsigned long long*)(stg + prow * 32 + pq * 4);
#pragma unroll
            for (int d = 0; d < 8; d++) {
                unsigned pa;
                asm("mapa.shared::cluster.u32 %0, %1, %2;" : "=r"(pa) : "r"(pOff0), "r"(d));
                asm volatile("st.shared::cluster.b64 [%0], %1;" :: "r"(pa), "l"(v) : "memory");
            }
        }
        CLUSTER_ARRIVE();   // #2: pushes issued + visible after wait
        CLUSTER_WAIT();

        // ---- phase C: layer-1 gates = b1 + Wih1@h0_new + Whh1@h1_old ----
#pragma unroll
        for (int g = 0; g < 4; g++)
#pragma unroll
            for (int r = 0; r < 4; r++) acc[g][r] = 0ull;

#pragma unroll 4
        for (int k2 = 0; k2 < 128; k2++) {
            uint4 wp = ws[4096 + k2 * 32 + jl];
            unsigned long long wg[4];
#pragma unroll
            for (int g = 0; g < 4; g++) {
                unsigned wv = ((const unsigned*)&wp)[g];
                wg[g] = f2u(__half22float2(*reinterpret_cast<__half2*>(&wv)));
            }
#pragma unroll
            for (int r = 0; r < 4; r++) {
                __half2 hh = *(const __half2*)(h0b + (4 * rg + r) * 256 + 2 * k2);
                unsigned long long hv = f2u(__half22float2(hh));
                fma2(acc[0][r], wg[0], hv);
                fma2(acc[1][r], wg[1], hv);
                fma2(acc[2][r], wg[2], hv);
                fma2(acc[3][r], wg[3], hv);
            }
        }
#pragma unroll 4
        for (int k2 = 0; k2 < 128; k2++) {
            uint4 wp = ws[8192 + k2 * 32 + jl];
            unsigned long long wg[4];
#pragma unroll
            for (int g = 0; g < 4; g++) {
                unsigned wv = ((const unsigned*)&wp)[g];
                wg[g] = f2u(__half22float2(*reinterpret_cast<__half2*>(&wv)));
            }
#pragma unroll
            for (int r = 0; r < 4; r++) {
                __half2 hh = *(const __half2*)(h1b + (4 * rg + r) * 256 + 2 * k2);
                unsigned long long hv = f2u(__half22float2(hh));
                fma2(acc[0][r], wg[0], hv);
                fma2(acc[1][r], wg[1], hv);
                fma2(acc[2][r], wg[2], hv);
                fma2(acc[3][r], wg[3], hv);
            }
        }
        CLUSTER_ARRIVE();   // #3: done reading old h1b

#pragma unroll
        for (int r = 0; r < 4; r++) {
            float2 vi = u2f(acc[0][r]), vf = u2f(acc[1][r]);
            float2 vg = u2f(acc[2][r]), vo = u2f(acc[3][r]);
            float gi = b1v.x + vi.x + vi.y;
            float gf = b1v.y + vf.x + vf.y;
            float gg = b1v.z + vg.x + vg.y;
            float go = b1v.w + vo.x + vo.y;
            float iv = sigm(gi), fv = sigm(gf), gv = tanhf(gg), ov = sigm(go);
            c1[r] = fv * c1[r] + iv * gv;
            hn[r] = ov * tanhf(c1[r]);
        }
#pragma unroll
        for (int r = 0; r < 4; r++)
            stg[(4 * rg + r) * 32 + jl] = __float2half(hn[r]);
        __syncthreads();
        CLUSTER_WAIT();     // all CTAs done reading old h1b

        {
            unsigned long long v = *(const unsigned long long*)(stg + prow * 32 + pq * 4);
#pragma unroll
            for (int d = 0; d < 8; d++) {
                unsigned pa;
                asm("mapa.shared::cluster.u32 %0, %1, %2;" : "=r"(pa) : "r"(pOff1), "r"(d));
                asm volatile("st.shared::cluster.b64 [%0], %1;" :: "r"(pa), "l"(v) : "memory");
            }
        }
        CLUSTER_ARRIVE();   // #4
        CLUSTER_WAIT();

        // ---- output head: CTA 'rank' handles local rows 4*rank..4*rank+3 ----
        if (rg < 4) {
            int rowL = 4 * (int)rank + rg;
            float s = 0.0f;
#pragma unroll
            for (int m = 0; m < 8; m++)
                s += __half2float(h1b[rowL * 256 + jl + 32 * m]) * wo[m];
#pragma unroll
            for (int off = 16; off; off >>= 1)
                s += __shfl_down_sync(0xffffffffu, s, off);
            if (jl == 0)
                out[(baseRow + rowL) * T_ + t] = s + bo0;
        }
    }
}

// ---------------- launch ----------------
extern "C" void kernel_launch(void* const* d_in, const int* in_sizes, int n_in,
                              void* d_out, int out_size) {
    const float* x    = (const float*)d_in[0];
    const float* xst  = (const float*)d_in[1];
    const float* Wih0 = (const float*)d_in[2];
    const float* Whh0 = (const float*)d_in[3];
    const float* bih0 = (const float*)d_in[4];
    const float* bhh0 = (const float*)d_in[5];
    const float* Wih1 = (const float*)d_in[6];
    const float* Whh1 = (const float*)d_in[7];
    const float* bih1 = (const float*)d_in[8];
    const float* bhh1 = (const float*)d_in[9];
    const float* Ws   = (const float*)d_in[10];
    const float* bs   = (const float*)d_in[11];
    const float* Wo   = (const float*)d_in[12];
    const float* bo   = (const float*)d_in[13];
    float* out = (float*)d_out;

    cudaFuncSetAttribute(lstm_main, cudaFuncAttributeMaxDynamicSharedMemorySize,
                         SMEM_BYTES);

    k_pack<<<128, 256>>>(Whh0, 0);
    k_pack<<<128, 256>>>(Wih1, 1);
    k_pack<<<128, 256>>>(Whh1, 2);
    k_wih0t<<<16, 256>>>(Wih0);
    k_bias<<<1, 256>>>(bih0, bhh0, bih1, bhh1);
    k_h0<<<512, 256>>>(xst, Ws, bs);
    lstm_main<<<128, 256, SMEM_BYTES>>>(x, Wo, bo, out);
}

// round 8
// speedup vs baseline: 4.6952x; 4.6952x over previous
#include <cuda_runtime.h>
#include <cuda_fp16.h>

#define B_ 512
#define T_ 365
#define D_ 16
#define S_ 32
#define H_ 256

/* ---- SMEM layout (bytes) ---- */
#define S0 280              /* fp16 row stride of A0 / W0 (256 used + pad) */
#define S1 520              /* fp16 row stride of A1 / W1 (512 used + 8 pad) */
#define W0_OFF 0            /* 64*280*2 = 35840  */
#define W1_OFF 35840        /* 64*520*2 = 66560  */
#define A0_OFF 102400       /* 35840             */
#define A1_OFF 138240       /* 66560             */
#define GB_OFF 204800       /* 64*66*4 = 16896   */
#define WOS_OFF 221696      /* 256*4 = 1024      */
#define BS_OFF 222720       /* 2*64*4 = 512      */
#define XS_OFF 223232       /* 64*16*4 = 4096 fp32 x_t */
#define SMEM_BYTES 227328

/* ---- device globals ---- */
__device__ float  g_h0f[B_ * H_];
__device__ __half g_h0x[B_ * H_];
__device__ __half g_h1x[B_ * H_];
__device__ unsigned g_cnt[8];

/* ---- prep kernel: h0 = x_static @ Ws^T + bs; zero barrier counters ---- */
__global__ void k_h0(const float* __restrict__ xst, const float* __restrict__ Ws,
                     const float* __restrict__ bs) {
    int e = blockIdx.x * 256 + threadIdx.x;
    if (blockIdx.x == 0 && threadIdx.x < 8) g_cnt[threadIdx.x] = 0;
    if (e >= B_ * H_) return;
    int b = e >> 8, j = e & 255;
    float s = bs[j];
#pragma unroll
    for (int k = 0; k < S_; k++)
        s += xst[b * S_ + k] * Ws[j * S_ + k];
    g_h0f[e] = s;
    g_h0x[e] = __float2half(s);
}

/* ---- helpers ---- */
__device__ __forceinline__ unsigned su32(const void* p) {
    unsigned a;
    asm("{ .reg .u64 t; cvta.to.shared.u64 t, %1; cvt.u32.u64 %0, t; }" : "=r"(a) : "l"(p));
    return a;
}
__device__ __forceinline__ float sigm(float v) { return 1.0f / (1.0f + __expf(-v)); }

#define LDSM4(r0,r1,r2,r3,a) \
    asm volatile("ldmatrix.sync.aligned.m8n8.x4.shared.b16 {%0,%1,%2,%3}, [%4];" \
        : "=r"(r0), "=r"(r1), "=r"(r2), "=r"(r3) : "r"(a))
#define LDSM2(r0,r1,a) \
    asm volatile("ldmatrix.sync.aligned.m8n8.x2.shared.b16 {%0,%1}, [%2];" \
        : "=r"(r0), "=r"(r1) : "r"(a))
#define MMA(d,a0,a1,a2,a3,b0,b1) \
    asm volatile("mma.sync.aligned.m16n8k16.row.col.f32.f16.f16.f32 " \
        "{%0,%1,%2,%3},{%4,%5,%6,%7},{%8,%9},{%0,%1,%2,%3};" \
        : "+f"((d)[0]), "+f"((d)[1]), "+f"((d)[2]), "+f"((d)[3]) \
        : "r"(a0), "r"(a1), "r"(a2), "r"(a3), "r"(b0), "r"(b1))

__device__ __forceinline__ void run_gemm(unsigned a0A, unsigned a1A,
                                         unsigned w0A, unsigned w1A,
                                         unsigned w2A, unsigned w3A,
                                         int ksteps, float acc[2][4][4]) {
#pragma unroll 2
    for (int ks = 0; ks < ksteps; ks++) {
        unsigned p0,p1,p2,p3, q0,q1,q2,q3;
        LDSM4(p0,p1,p2,p3, a0A);
        LDSM4(q0,q1,q2,q3, a1A);
        unsigned b00,b01,b10,b11,b20,b21,b30,b31;
        LDSM2(b00,b01, w0A);
        LDSM2(b10,b11, w1A);
        LDSM2(b20,b21, w2A);
        LDSM2(b30,b31, w3A);
        MMA(acc[0][0], p0,p1,p2,p3, b00,b01);
        MMA(acc[0][1], p0,p1,p2,p3, b10,b11);
        MMA(acc[0][2], p0,p1,p2,p3, b20,b21);
        MMA(acc[0][3], p0,p1,p2,p3, b30,b31);
        MMA(acc[1][0], q0,q1,q2,q3, b00,b01);
        MMA(acc[1][1], q0,q1,q2,q3, b10,b11);
        MMA(acc[1][2], q0,q1,q2,q3, b20,b21);
        MMA(acc[1][3], q0,q1,q2,q3, b30,b31);
        a0A += 32; a1A += 32;
        w0A += 32; w1A += 32; w2A += 32; w3A += 32;
    }
}

/* group barrier: monotonic counter; release-RMW arrive, acquire spin.
   Race-free given all 16 group CTAs co-resident (128 CTAs, 1/SM). */
__device__ __forceinline__ void gbar(int g, unsigned target) {
    __threadfence();
    __syncthreads();
    if (threadIdx.x == 0) {
        asm volatile("red.release.gpu.global.add.u32 [%0], %1;"
                     :: "l"(&g_cnt[g]), "r"(1u) : "memory");
        unsigned v;
        do {
            asm volatile("ld.acquire.gpu.global.u32 %0, [%1];"
                         : "=r"(v) : "l"(&g_cnt[g]) : "memory");
        } while (v < target);
    }
    __syncthreads();
}

/* ---- main persistent kernel: 128 CTAs = 8 groups x 16 ranks ---- */
__global__ void __launch_bounds__(128, 1)
lstm_main(const float* __restrict__ x,
          const float* __restrict__ Wih0, const float* __restrict__ Whh0,
          const float* __restrict__ Wih1, const float* __restrict__ Whh1,
          const float* __restrict__ bih0, const float* __restrict__ bhh0,
          const float* __restrict__ bih1, const float* __restrict__ bhh1,
          const float* __restrict__ Wo, const float* __restrict__ bo,
          float* __restrict__ out)
{
    extern __shared__ char smem[];
    const int tid  = threadIdx.x;
    const int lane = tid & 31;
    const int wid  = tid >> 5;
    const int mh = wid & 1, nh = wid >> 1;
    const int group = blockIdx.x >> 4;
    const int rank  = blockIdx.x & 15;

    __half* W0s = (__half*)(smem + W0_OFF);
    __half* W1s = (__half*)(smem + W1_OFF);
    float*  GBf = (float*)(smem + GB_OFF);
    float*  wos = (float*)(smem + WOS_OFF);
    float*  b0s = (float*)(smem + BS_OFF);
    float*  b1s = b0s + 64;
    float*  xsf = (float*)(smem + XS_OFF);

    /* ---- build weight slices in SMEM (one-time) ---- */
    for (int e = tid; e < 64 * S0; e += 128) {
        int n = e / S0, k = e - n * S0;
        int wr = (n >> 4) * H_ + rank * 16 + (n & 15);
        float v = (k < 256) ? Whh0[wr * H_ + k] : 0.0f;
        W0s[e] = __float2half(v);
    }
    for (int e = tid; e < 64 * S1; e += 128) {
        int n = e / S1, k = e - n * S1;
        int wr = (n >> 4) * H_ + rank * 16 + (n & 15);
        float v = 0.0f;
        if (k < 256) v = Wih1[wr * H_ + k];
        else if (k < 512) v = Whh1[wr * H_ + (k - 256)];
        W1s[e] = __float2half(v);
    }
    if (tid < 64) {
        int wr = (tid >> 4) * H_ + rank * 16 + (tid & 15);
        b0s[tid] = bih0[wr] + bhh0[wr];
        b1s[tid] = bih1[wr] + bhh1[wr];
    }
    for (int e = tid; e < 256; e += 128) wos[e] = Wo[e];
    const float bo0 = __ldg(bo);

    /* ---- fp32 Wih0 slice in registers (constant over t) ---- */
    const int jl = tid & 15;
    const int rb = (tid >> 4) * 8;
    float wreg[4][D_];
#pragma unroll
    for (int g = 0; g < 4; g++) {
        const float* wp = Wih0 + (size_t)(g * H_ + rank * 16 + jl) * D_;
#pragma unroll
        for (int k = 0; k < D_; k++) wreg[g][k] = __ldg(wp + k);
    }

    /* ---- initial A fill (h0 = h1 = static projection) ---- */
    for (int e = tid; e < 2048; e += 128) {
        int row = e >> 5, ch = e & 31;
        uint4 v = *((const uint4*)(g_h0x + (size_t)(group * 64 + row) * H_) + ch);
        *(uint4*)(smem + A0_OFF + row * (S0 * 2) + ch * 16) = v;
        *(uint4*)(smem + A1_OFF + row * (S1 * 2) + ch * 16) = v;
        *(uint4*)(smem + A1_OFF + row * (S1 * 2) + 512 + ch * 16) = v;
    }

    /* ---- c-state registers: thread owns 8 rows x 1 j ---- */
    float c0[8], c1[8];
#pragma unroll
    for (int rr = 0; rr < 8; rr++) {
        float v = g_h0f[(size_t)(group * 64 + rb + rr) * H_ + rank * 16 + jl];
        c0[rr] = v; c1[rr] = v;
    }
    __syncthreads();

    /* FIX (R7 race): no rank may overwrite g_h0x (step-0 epilogue) until every
       rank in the group finished reading the initial state above. */
    gbar(group, 16);

    /* per-thread ldmatrix base addresses */
    const unsigned sb = su32(smem);
    const int aRow = mh * 32 + (lane & 7) + ((lane >> 3) & 1) * 8;
    const int aCol = (lane >> 4) * 8;
    const unsigned a0m0 = sb + A0_OFF + (unsigned)((aRow)      * S0 + aCol) * 2;
    const unsigned a0m1 = sb + A0_OFF + (unsigned)((aRow + 16) * S0 + aCol) * 2;
    const unsigned a1m0 = sb + A1_OFF + (unsigned)((aRow)      * S1 + aCol) * 2;
    const unsigned a1m1 = sb + A1_OFF + (unsigned)((aRow + 16) * S1 + aCol) * 2;
    const int wCol = ((lane >> 3) & 1) * 8;
    unsigned w0a[4], w1a[4];
#pragma unroll
    for (int nt = 0; nt < 4; nt++) {
        int nrow = (nh * 4 + nt) * 8 + (lane & 7);
        w0a[nt] = sb + W0_OFF + (unsigned)(nrow * S0 + wCol) * 2;
        w1a[nt] = sb + W1_OFF + (unsigned)(nrow * S1 + wCol) * 2;
    }

    __half* h0slice = g_h0x + (size_t)(group * 64) * H_ + rank * 16 + jl;
    __half* h1slice = g_h1x + (size_t)(group * 64) * H_ + rank * 16 + jl;
    unsigned bar_t = 16;

    for (int t = 0; t < T_; t++) {
        /* stage x_t (fp32) into xsf[64][16] */
        {
            int row = tid >> 1, d8 = (tid & 1) * 8;
            const float4* xp = (const float4*)
                (x + (size_t)(group * 64 + row) * T_ * D_ + (size_t)t * D_ + d8);
            float4 a = __ldg(xp), b = __ldg(xp + 1);
            *(float4*)(xsf + row * D_ + d8)     = a;
            *(float4*)(xsf + row * D_ + d8 + 4) = b;
        }
        __syncthreads();

        /* ===== layer 0: gates = h0 @ Whh0^T  (x-path added in epilogue) ===== */
        float acc[2][4][4];
#pragma unroll
        for (int a = 0; a < 2; a++)
#pragma unroll
            for (int b = 0; b < 4; b++)
#pragma unroll
                for (int c = 0; c < 4; c++) acc[a][b][c] = 0.0f;
        run_gemm(a0m0, a0m1, w0a[0], w0a[1], w0a[2], w0a[3], 16, acc);

        /* fragments -> gbuf */
#pragma unroll
        for (int mt = 0; mt < 2; mt++)
#pragma unroll
            for (int nt = 0; nt < 4; nt++) {
                int m = mh * 32 + mt * 16 + (lane >> 2);
                int n = nh * 32 + nt * 8 + (lane & 3) * 2;
                *(float2*)&GBf[m * 66 + n]       = make_float2(acc[mt][nt][0], acc[mt][nt][1]);
                *(float2*)&GBf[(m + 8) * 66 + n] = make_float2(acc[mt][nt][2], acc[mt][nt][3]);
            }
        __syncthreads();

        /* epilogue 0: add fp32 x @ Wih0^T + bias, nonlinearity, update c0, emit h0 */
#pragma unroll
        for (int rr = 0; rr < 8; rr++) {
            int r = rb + rr;
            float xi = 0.f, xf = 0.f, xg = 0.f, xo = 0.f;
            const float* xr = xsf + r * D_;
#pragma unroll
            for (int k = 0; k < D_; k++) {
                float xv = xr[k];
                xi += wreg[0][k] * xv;
                xf += wreg[1][k] * xv;
                xg += wreg[2][k] * xv;
                xo += wreg[3][k] * xv;
            }
            float gi = GBf[r * 66 +       jl] + b0s[jl]      + xi;
            float gf = GBf[r * 66 + 16 +  jl] + b0s[16 + jl] + xf;
            float gg = GBf[r * 66 + 32 +  jl] + b0s[32 + jl] + xg;
            float go = GBf[r * 66 + 48 +  jl] + b0s[48 + jl] + xo;
            float iv = sigm(gi), fv = sigm(gf), gv = tanhf(gg), ov = sigm(go);
            c0[rr] = fv * c0[rr] + iv * gv;
            h0slice[(size_t)r * H_] = __float2half(ov * tanhf(c0[rr]));
        }
        gbar(group, bar_t += 16);

        /* reload full h0_new -> A0[0..255] and A1[0..255] */
        for (int e = tid; e < 2048; e += 128) {
            int row = e >> 5, ch = e & 31;
            uint4 v = __ldcg((const uint4*)(g_h0x + (size_t)(group * 64 + row) * H_) + ch);
            *(uint4*)(smem + A0_OFF + row * (S0 * 2) + ch * 16) = v;
            *(uint4*)(smem + A1_OFF + row * (S1 * 2) + ch * 16) = v;
        }
        __syncthreads();

        /* ===== layer 1: gates = [h0new|h1old] @ [Wih1|Whh1]^T ===== */
#pragma unroll
        for (int a = 0; a < 2; a++)
#pragma unroll
            for (int b = 0; b < 4; b++)
#pragma unroll
                for (int c = 0; c < 4; c++) acc[a][b][c] = 0.0f;
        run_gemm(a1m0, a1m1, w1a[0], w1a[1], w1a[2], w1a[3], 32, acc);

#pragma unroll
        for (int mt = 0; mt < 2; mt++)
#pragma unroll
            for (int nt = 0; nt < 4; nt++) {
                int m = mh * 32 + mt * 16 + (lane >> 2);
                int n = nh * 32 + nt * 8 + (lane & 3) * 2;
                *(float2*)&GBf[m * 66 + n]       = make_float2(acc[mt][nt][0], acc[mt][nt][1]);
                *(float2*)&GBf[(m + 8) * 66 + n] = make_float2(acc[mt][nt][2], acc[mt][nt][3]);
            }
        __syncthreads();

        /* epilogue 1 */
#pragma unroll
        for (int rr = 0; rr < 8; rr++) {
            int r = rb + rr;
            float gi = GBf[r * 66 +       jl] + b1s[jl];
            float gf = GBf[r * 66 + 16 +  jl] + b1s[16 + jl];
            float gg = GBf[r * 66 + 32 +  jl] + b1s[32 + jl];
            float go = GBf[r * 66 + 48 +  jl] + b1s[48 + jl];
            float iv = sigm(gi), fv = sigm(gf), gv = tanhf(gg), ov = sigm(go);
            c1[rr] = fv * c1[rr] + iv * gv;
            h1slice[(size_t)r * H_] = __float2half(ov * tanhf(c1[rr]));
        }
        gbar(group, bar_t += 16);

        /* reload full h1_new -> A1[256..511] */
        for (int e = tid; e < 2048; e += 128) {
            int row = e >> 5, ch = e & 31;
            uint4 v = __ldcg((const uint4*)(g_h1x + (size_t)(group * 64 + row) * H_) + ch);
            *(uint4*)(smem + A1_OFF + row * (S1 * 2) + 512 + ch * 16) = v;
        }
        __syncthreads();

        /* output head: out[row, t] = h1 . Wo + bo  (2 threads per row) */
        {
            int hrow = tid >> 1, hs = tid & 1;
            const __half2* hp =
                (const __half2*)(smem + A1_OFF + hrow * (S1 * 2) + 512) + hs * 64;
            float s = 0.0f;
#pragma unroll
            for (int q = 0; q < 64; q++) {
                float2 v = __half22float2(hp[q]);
                s += v.x * wos[hs * 128 + 2 * q] + v.y * wos[hs * 128 + 2 * q + 1];
            }
            s += __shfl_xor_sync(0xffffffffu, s, 1);
            if (hs == 0)
                out[(size_t)(group * 64 + hrow) * T_ + t] = s + bo0;
        }
        __syncthreads();   /* head reads done before next-step x staging */
    }
}

/* ---------------- launch ---------------- */
extern "C" void kernel_launch(void* const* d_in, const int* in_sizes, int n_in,
                              void* d_out, int out_size) {
    const float* x    = (const float*)d_in[0];
    const float* xst  = (const float*)d_in[1];
    const float* Wih0 = (const float*)d_in[2];
    const float* Whh0 = (const float*)d_in[3];
    const float* bih0 = (const float*)d_in[4];
    const float* bhh0 = (const float*)d_in[5];
    const float* Wih1 = (const float*)d_in[6];
    const float* Whh1 = (const float*)d_in[7];
    const float* bih1 = (const float*)d_in[8];
    const float* bhh1 = (const float*)d_in[9];
    const float* Ws   = (const float*)d_in[10];
    const float* bs   = (const float*)d_in[11];
    const float* Wo   = (const float*)d_in[12];
    const float* bo   = (const float*)d_in[13];
    float* out = (float*)d_out;

    cudaFuncSetAttribute(lstm_main, cudaFuncAttributeMaxDynamicSharedMemorySize,
                         SMEM_BYTES);

    k_h0<<<(B_ * H_ + 255) / 256, 256>>>(xst, Ws, bs);
    lstm_main<<<128, 128, SMEM_BYTES>>>(x, Wih0, Whh0, Wih1, Whh1,
                                        bih0, bhh0, bih1, bhh1, Wo, bo, out);
}

// round 9
// speedup vs baseline: 7.1785x; 1.5289x over previous
#include <cuda_runtime.h>
#include <cuda_fp16.h>

#define B_ 512
#define T_ 365
#define D_ 16
#define S_ 32
#define H_ 256

/* ---- SMEM layout (bytes) ---- */
#define S0 296              /* fp16 row stride of A0/W0: 256 h + 16 x_hi + 16 x_res + 8 pad */
#define S1 520              /* fp16 row stride of A1/W1: 512 + 8 pad */
#define W0_OFF 0            /* 64*296*2 = 37888 */
#define W1_OFF 37888        /* 64*520*2 = 66560 */
#define A0_OFF 104448       /* 37888 */
#define A1_OFF 142336       /* 66560 */
#define GB_OFF 208896       /* 64*66*4 = 16896 */
#define BS_OFF 225792       /* 2*64*4 = 512 */
#define SMEM_BYTES 226304   /* <= 232448 */

/* ---- device globals ---- */
__device__ float  g_h0f[B_ * H_];
__device__ __half g_h0x[B_ * H_];
__device__ __half g_h1x[B_ * H_];
__device__ unsigned g_cnt[16];   /* [g]=B1, [8+g]=B2 */

/* ---- prep kernel ---- */
__global__ void k_h0(const float* __restrict__ xst, const float* __restrict__ Ws,
                     const float* __restrict__ bs) {
    int e = blockIdx.x * 256 + threadIdx.x;
    if (blockIdx.x == 0 && threadIdx.x < 16) g_cnt[threadIdx.x] = 0;
    if (e >= B_ * H_) return;
    int b = e >> 8, j = e & 255;
    float s = bs[j];
#pragma unroll
    for (int k = 0; k < S_; k++)
        s += xst[b * S_ + k] * Ws[j * S_ + k];
    g_h0f[e] = s;
    __half h = __float2half(s);
    g_h0x[e] = h;
    g_h1x[e] = h;
}

/* ---- helpers ---- */
__device__ __forceinline__ unsigned su32(const void* p) {
    unsigned a;
    asm("{ .reg .u64 t; cvta.to.shared.u64 t, %1; cvt.u32.u64 %0, t; }" : "=r"(a) : "l"(p));
    return a;
}
__device__ __forceinline__ float sigm(float x) {
    return __fdividef(1.0f, 1.0f + __expf(-x));
}
__device__ __forceinline__ float tanhe(float x) {
    return __fdividef(2.0f, 1.0f + __expf(-2.0f * x)) - 1.0f;
}

#define LDSM4(r0,r1,r2,r3,a) \
    asm volatile("ldmatrix.sync.aligned.m8n8.x4.shared.b16 {%0,%1,%2,%3}, [%4];" \
        : "=r"(r0), "=r"(r1), "=r"(r2), "=r"(r3) : "r"(a))
#define MMA(d,a0,a1,a2,a3,b0,b1) \
    asm volatile("mma.sync.aligned.m16n8k16.row.col.f32.f16.f16.f32 " \
        "{%0,%1,%2,%3},{%4,%5,%6,%7},{%8,%9},{%0,%1,%2,%3};" \
        : "+f"((d)[0]), "+f"((d)[1]), "+f"((d)[2]), "+f"((d)[3]) \
        : "r"(a0), "r"(a1), "r"(a2), "r"(a3), "r"(b0), "r"(b1))

/* warp tile M32xN16: two A 16-row frags, one LDSM4 B covering n16xk16 */
__device__ __forceinline__ void run_gemm(unsigned aA0, unsigned aA1, unsigned wA,
                                         int ksteps, float acc[2][2][4]) {
#pragma unroll 2
    for (int ks = 0; ks < ksteps; ks++) {
        unsigned p0,p1,p2,p3, q0,q1,q2,q3, b0,b1,b2,b3;
        LDSM4(p0,p1,p2,p3, aA0);
        LDSM4(q0,q1,q2,q3, aA1);
        LDSM4(b0,b1,b2,b3, wA);
        MMA(acc[0][0], p0,p1,p2,p3, b0,b1);
        MMA(acc[0][1], p0,p1,p2,p3, b2,b3);
        MMA(acc[1][0], q0,q1,q2,q3, b0,b1);
        MMA(acc[1][1], q0,q1,q2,q3, b2,b3);
        aA0 += 32; aA1 += 32; wA += 32;
    }
}

__device__ __forceinline__ void frag_store(float* GBf, const float acc[2][2][4],
                                           int mh, int nq, int lane) {
#pragma unroll
    for (int mt = 0; mt < 2; mt++)
#pragma unroll
        for (int nt = 0; nt < 2; nt++) {
            int m = mh * 32 + mt * 16 + (lane >> 2);
            int n = nq * 16 + nt * 8 + (lane & 3) * 2;
            *(float2*)&GBf[m * 66 + n]       = make_float2(acc[mt][nt][0], acc[mt][nt][1]);
            *(float2*)&GBf[(m + 8) * 66 + n] = make_float2(acc[mt][nt][2], acc[mt][nt][3]);
        }
}

/* split barrier: release arrive / acquire wait on a monotonic counter */
__device__ __forceinline__ void g_arrive(unsigned* c) {
    __threadfence();
    __syncthreads();
    if (threadIdx.x == 0)
        asm volatile("red.release.gpu.global.add.u32 [%0], %1;" :: "l"(c), "r"(1u) : "memory");
}
__device__ __forceinline__ void g_wait(unsigned* c, unsigned target) {
    if (threadIdx.x == 0) {
        unsigned v;
        do {
            asm volatile("ld.acquire.gpu.global.u32 %0, [%1];" : "=r"(v) : "l"(c) : "memory");
        } while (v < target);
    }
    __syncthreads();
}

/* stage x_t as hi/res fp16 pair into A0 cols 256..287 */
__device__ __forceinline__ void stage_x(char* smem, const float* x, int group,
                                        int t, int tid) {
    int row = tid >> 2, kq = (tid & 3) * 4;
    const float4 v = __ldg((const float4*)
        (x + (size_t)(group * 64 + row) * T_ * D_ + (size_t)t * D_ + kq));
    __half h0 = __float2half(v.x), h1 = __float2half(v.y),
           h2 = __float2half(v.z), h3 = __float2half(v.w);
    float r0 = v.x - __half2float(h0), r1 = v.y - __half2float(h1),
          r2 = v.z - __half2float(h2), r3 = v.w - __half2float(h3);
    __half2 hA = __halves2half2(h0, h1), hB = __halves2half2(h2, h3);
    __half2 rA = __floats2half2_rn(r0, r1), rB = __floats2half2_rn(r2, r3);
    char* base = smem + A0_OFF + row * (S0 * 2);
    *(uint2*)(base + (256 + kq) * 2) = make_uint2(*(unsigned*)&hA, *(unsigned*)&hB);
    *(uint2*)(base + (272 + kq) * 2) = make_uint2(*(unsigned*)&rA, *(unsigned*)&rB);
}

/* ---- main persistent kernel: 128 CTAs = 8 groups x 16 ranks, 256 thr ---- */
__global__ void __launch_bounds__(256, 1)
lstm_main(const float* __restrict__ x,
          const float* __restrict__ Wih0, const float* __restrict__ Whh0,
          const float* __restrict__ Wih1, const float* __restrict__ Whh1,
          const float* __restrict__ bih0, const float* __restrict__ bhh0,
          const float* __restrict__ bih1, const float* __restrict__ bhh1,
          const float* __restrict__ Wo, const float* __restrict__ bo,
          float* __restrict__ out)
{
    extern __shared__ char smem[];
    const int tid  = threadIdx.x;
    const int lane = tid & 31;
    const int wid  = tid >> 5;
    const int mh = wid & 1, nq = wid >> 1;
    const int group = blockIdx.x >> 4;
    const int rank  = blockIdx.x & 15;
    const int jl = tid & 15;
    const int rgrp = tid >> 4;

    __half* W0s = (__half*)(smem + W0_OFF);
    __half* W1s = (__half*)(smem + W1_OFF);
    float*  GBf = (float*)(smem + GB_OFF);
    float*  b0s = (float*)(smem + BS_OFF);
    float*  b1s = b0s + 64;

    unsigned* cB1 = &g_cnt[group];
    unsigned* cB2 = &g_cnt[8 + group];

    /* ---- one-time weight staging ---- */
    for (int e = tid; e < 64 * S0; e += 256) {
        int n = e / S0, k = e - n * S0;
        int wr = (n >> 4) * H_ + rank * 16 + (n & 15);
        float v = 0.0f;
        if (k < 256)      v = Whh0[wr * H_ + k];
        else if (k < 272) v = Wih0[wr * D_ + (k - 256)];
        else if (k < 288) v = Wih0[wr * D_ + (k - 272)];
        W0s[e] = __float2half(v);
    }
    for (int e = tid; e < 64 * S1; e += 256) {
        int n = e / S1, k = e - n * S1;
        int wr = (n >> 4) * H_ + rank * 16 + (n & 15);
        float v = 0.0f;
        if (k < 256)      v = Wih1[wr * H_ + k];
        else if (k < 512) v = Whh1[wr * H_ + (k - 256)];
        W1s[e] = __float2half(v);
    }
    if (tid < 64) {
        int wr = (tid >> 4) * H_ + rank * 16 + (tid & 15);
        b0s[tid] = bih0[wr] + bhh0[wr];
        b1s[tid] = bih1[wr] + bhh1[wr];
    }
    const float woreg = __ldg(Wo + rank * 16 + jl);
    const float bo0   = __ldg(bo);

    /* ---- zero this group's output rows (head uses atomicAdd) ---- */
    {
        float* ob = out + (size_t)group * 64 * T_;
        for (int i = rank * 256 + tid; i < 64 * T_; i += 4096) ob[i] = 0.0f;
    }

    /* ---- initial A0 <- h0 init; stage x(0) ---- */
    for (int e = tid; e < 2048; e += 256) {
        int row = e >> 5, ch = e & 31;
        uint4 v = *((const uint4*)(g_h0x + (size_t)(group * 64 + row) * H_) + ch);
        *(uint4*)(smem + A0_OFF + row * (S0 * 2) + ch * 16) = v;
    }
    stage_x(smem, x, group, 0, tid);

    /* ---- c-state: 4 rows x 1 j per thread ---- */
    float c0[4], c1[4];
#pragma unroll
    for (int rr = 0; rr < 4; rr++) {
        float v = g_h0f[(size_t)(group * 64 + rgrp * 4 + rr) * H_ + rank * 16 + jl];
        c0[rr] = v; c1[rr] = v;
    }
    __syncthreads();

    /* prologue barrier: initial reads done group-wide before first writes */
    g_arrive(cB1);
    g_wait(cB1, 16);

    /* ldmatrix addressing */
    const unsigned sb = su32(smem);
    const int aRow = mh * 32 + (lane & 7) + ((lane >> 3) & 1) * 8;
    const int aCol = (lane >> 4) * 8;
    const unsigned a0m0 = sb + A0_OFF + (unsigned)(aRow * S0 + aCol) * 2;
    const unsigned a0m1 = sb + A0_OFF + (unsigned)((aRow + 16) * S0 + aCol) * 2;
    const unsigned a1m0 = sb + A1_OFF + (unsigned)(aRow * S1 + aCol) * 2;
    const unsigned a1m1 = sb + A1_OFF + (unsigned)((aRow + 16) * S1 + aCol) * 2;
    const int nrow = nq * 16 + ((lane >> 4) & 1) * 8 + (lane & 7);
    const int wCol = ((lane >> 3) & 1) * 8;
    const unsigned w0a = sb + W0_OFF + (unsigned)(nrow * S0 + wCol) * 2;
    const unsigned w1a = sb + W1_OFF + (unsigned)(nrow * S1 + wCol) * 2;

    unsigned b1t = 16, b2t = 0;

    for (int t = 0; t < T_; t++) {
        /* 1) GEMM0(t): [h0(t-1)|x_hi|x_res] @ [Whh0|Wih0|Wih0]^T (18 ksteps) */
        float acc[2][2][4];
#pragma unroll
        for (int a = 0; a < 2; a++)
#pragma unroll
            for (int b = 0; b < 2; b++)
#pragma unroll
                for (int c = 0; c < 4; c++) acc[a][b][c] = 0.0f;
        run_gemm(a0m0, a0m1, w0a, 18, acc);
        frag_store(GBf, acc, mh, nq, lane);
        __syncthreads();

        /* 2) wait B2(t-1) (overlapped by GEMM0 above); reload h1(t-1) -> A1hi */
        g_wait(cB2, b2t);
        for (int e = tid; e < 2048; e += 256) {
            int row = e >> 5, ch = e & 31;
            uint4 v = __ldcg((const uint4*)(g_h1x + (size_t)(group * 64 + row) * H_) + ch);
            *(uint4*)(smem + A1_OFF + row * (S1 * 2) + 512 + ch * 16) = v;
        }
        __syncthreads();

        /* 3) epilogue 0 -> h0(t), publish slice, arrive B1(t) */
#pragma unroll
        for (int rr = 0; rr < 4; rr++) {
            int r = rgrp * 4 + rr;
            float gi = GBf[r * 66 +      jl] + b0s[jl];
            float gf = GBf[r * 66 + 16 + jl] + b0s[16 + jl];
            float gg = GBf[r * 66 + 32 + jl] + b0s[32 + jl];
            float go = GBf[r * 66 + 48 + jl] + b0s[48 + jl];
            float iv = sigm(gi), fv = sigm(gf), gv = tanhe(gg), ov = sigm(go);
            c0[rr] = fv * c0[rr] + iv * gv;
            g_h0x[(size_t)(group * 64 + r) * H_ + rank * 16 + jl] =
                __float2half(ov * tanhe(c0[rr]));
        }
        g_arrive(cB1);

        /* 4) GEMM1a(t): h1(t-1) @ Whh1^T (16 ksteps) — overlaps B1 skew */
#pragma unroll
        for (int a = 0; a < 2; a++)
#pragma unroll
            for (int b = 0; b < 2; b++)
#pragma unroll
                for (int c = 0; c < 4; c++) acc[a][b][c] = 0.0f;
        run_gemm(a1m0 + 512, a1m1 + 512, w1a + 512, 16, acc);

        /* 5) wait B1(t); reload h0(t) -> A0 (next GEMM0) and A1lo */
        b1t += 16;
        g_wait(cB1, b1t);
        for (int e = tid; e < 2048; e += 256) {
            int row = e >> 5, ch = e & 31;
            uint4 v = __ldcg((const uint4*)(g_h0x + (size_t)(group * 64 + row) * H_) + ch);
            *(uint4*)(smem + A0_OFF + row * (S0 * 2) + ch * 16) = v;
            *(uint4*)(smem + A1_OFF + row * (S1 * 2) + ch * 16) = v;
        }
        __syncthreads();

        /* 6) GEMM1b(t): h0(t) @ Wih1^T accumulate */
        run_gemm(a1m0, a1m1, w1a, 16, acc);
        frag_store(GBf, acc, mh, nq, lane);
        __syncthreads();

        /* 7) epilogue 1 -> h1(t), head partials from registers, arrive B2(t) */
        float p[4];
#pragma unroll
        for (int rr = 0; rr < 4; rr++) {
            int r = rgrp * 4 + rr;
            float gi = GBf[r * 66 +      jl] + b1s[jl];
            float gf = GBf[r * 66 + 16 + jl] + b1s[16 + jl];
            float gg = GBf[r * 66 + 32 + jl] + b1s[32 + jl];
            float go = GBf[r * 66 + 48 + jl] + b1s[48 + jl];
            float iv = sigm(gi), fv = sigm(gf), gv = tanhe(gg), ov = sigm(go);
            c1[rr] = fv * c1[rr] + iv * gv;
            float h = ov * tanhe(c1[rr]);
            g_h1x[(size_t)(group * 64 + r) * H_ + rank * 16 + jl] = __float2half(h);
            p[rr] = h * woreg;
        }
#pragma unroll
        for (int off = 1; off < 16; off <<= 1)
#pragma unroll
            for (int rr = 0; rr < 4; rr++)
                p[rr] += __shfl_xor_sync(0xffffffffu, p[rr], off);
        if (jl == 0) {
#pragma unroll
            for (int rr = 0; rr < 4; rr++) {
                float v = p[rr];
                if (rank == 0) v += bo0;
                atomicAdd(&out[(size_t)(group * 64 + rgrp * 4 + rr) * T_ + t], v);
            }
        }
        g_arrive(cB2);
        b2t += 16;

        /* 8) stage x(t+1) — next GEMM0 overlaps the B2 wait */
        if (t + 1 < T_) stage_x(smem, x, group, t + 1, tid);
        __syncthreads();
    }
}

/* ---------------- launch ---------------- */
extern "C" void kernel_launch(void* const* d_in, const int* in_sizes, int n_in,
                              void* d_out, int out_size) {
    const float* x    = (const float*)d_in[0];
    const float* xst  = (const float*)d_in[1];
    const float* Wih0 = (const float*)d_in[2];
    const float* Whh0 = (const float*)d_in[3];
    const float* bih0 = (const float*)d_in[4];
    const float* bhh0 = (const float*)d_in[5];
    const float* Wih1 = (const float*)d_in[6];
    const float* Whh1 = (const float*)d_in[7];
    const float* bih1 = (const float*)d_in[8];
    const float* bhh1 = (const float*)d_in[9];
    const float* Ws   = (const float*)d_in[10];
    const float* bs   = (const float*)d_in[11];
    const float* Wo   = (const float*)d_in[12];
    const float* bo   = (const float*)d_in[13];
    float* out = (float*)d_out;

    cudaFuncSetAttribute(lstm_main, cudaFuncAttributeMaxDynamicSharedMemorySize,
                         SMEM_BYTES);

    k_h0<<<(B_ * H_ + 255) / 256, 256>>>(xst, Ws, bs);
    lstm_main<<<128, 256, SMEM_BYTES>>>(x, Wih0, Whh0, Wih1, Whh1,
                                        bih0, bhh0, bih1, bhh1, Wo, bo, out);
}